// round 11
// baseline (speedup 1.0000x reference)
#include <cuda_runtime.h>
#include <cuda_bf16.h>
#include <cstdint>

#define N_NODES 100000
#define N_EDGES 3200000
#define F_IN 256
#define CH 16
#define FCN 64

#define SCAN_B 1024
#define SCAN_NB ((N_NODES + SCAN_B - 1) / SCAN_B)   // 98
#define READY_BIT 0x40000000

#define REC_CAP (N_EDGES + 8 * N_NODES)              // padded CSR capacity

// Scratch: __device__ globals (no allocation allowed). Statically zeroed at
// load; kernels restore zero state each call (scan re-zeros hist4; scatter
// resets bpub). CSR padding slots are never written -> stay (0,0) forever:
// src_off=0, w=0 contributes nothing (gathers L1-hot row 0).
__device__ __align__(128) float g_h[N_NODES * CH];
__device__ __align__(128) int2  g_rec[REC_CAP];       // (src*64, w_bits), dst-grouped
__device__ __align__(16) int4 g_hist4[N_NODES];       // per-(dst,sub) counts
__device__ __align__(16) int4 g_cursor4[N_NODES];     // per-(dst,sub) cursors
__device__ int g_ptr[N_NODES + 1];                    // padded-degree prefix
__device__ int g_bpub[SCAN_NB];                       // zero-init; reset in scatter
__device__ int g_idx_is64;                            // published by k1

// ---------------------------------------------------------------------------
// f32x2 helpers: packed dual fp32 FMA (PTX-only on Blackwell; bit-identical
// to two scalar FFMA).
// ---------------------------------------------------------------------------
__device__ __forceinline__ void fma2(unsigned long long& acc,
                                     unsigned long long a, unsigned long long b) {
    asm("fma.rn.f32x2 %0, %1, %2, %0;" : "+l"(acc) : "l"(a), "l"(b));
}
__device__ __forceinline__ unsigned long long pack2(float x) {
    unsigned long long r;
    asm("mov.b64 %0, {%1, %1};" : "=l"(r) : "f"(x));
    return r;
}
__device__ __forceinline__ unsigned long long pack2f(float lo, float hi) {
    unsigned long long r;
    asm("mov.b64 %0, {%1, %2};" : "=l"(r) : "f"(lo), "f"(hi));
    return r;
}
__device__ __forceinline__ void unpack2(unsigned long long v, float& lo, float& hi) {
    asm("mov.b64 {%0, %1}, %2;" : "=f"(lo), "=f"(hi) : "l"(v));
}

// ---------------------------------------------------------------------------
// log-halving cross-lane reduction of 16 per-channel partials over 32 lanes.
// 16 shfls instead of 80. Channel chan_of_lane(lane) ends on lane (and l^16).
// ---------------------------------------------------------------------------
__device__ __forceinline__ float reduce16(const float* r, int lane) {
    const unsigned FULL = 0xFFFFFFFFu;
    float t[8];
    bool hi = (lane & 1);
#pragma unroll
    for (int j = 0; j < 8; j++) {
        float give = hi ? r[j] : r[j + 8];
        float keep = hi ? r[j + 8] : r[j];
        t[j] = keep + __shfl_xor_sync(FULL, give, 1);
    }
    float u[4];
    hi = (lane & 2);
#pragma unroll
    for (int j = 0; j < 4; j++) {
        float give = hi ? t[j] : t[j + 4];
        float keep = hi ? t[j + 4] : t[j];
        u[j] = keep + __shfl_xor_sync(FULL, give, 2);
    }
    hi = (lane & 4);
    float g0 = hi ? u[0] : u[2];
    float k0 = hi ? u[2] : u[0];
    float v0 = k0 + __shfl_xor_sync(FULL, g0, 4);
    float g1 = hi ? u[1] : u[3];
    float k1 = hi ? u[3] : u[1];
    float v1 = k1 + __shfl_xor_sync(FULL, g1, 4);

    hi = (lane & 8);
    float g2 = hi ? v0 : v1;
    float k2 = hi ? v1 : v0;
    float w = k2 + __shfl_xor_sync(FULL, g2, 8);

    w += __shfl_xor_sync(FULL, w, 16);
    return w;
}

__device__ __forceinline__ int chan_of_lane(int lane) {
    return ((lane & 1) << 3) | ((lane & 2) << 1) | ((lane & 4) >> 1) | ((lane & 8) >> 3);
}

// ---------------------------------------------------------------------------
// Launch 1: h = x @ w_gcn (2 nodes/warp, f32x2 packed FMA, channel-paired
// weights in smem) FUSED with 4-way sub histogram + dtype probe.
// ---------------------------------------------------------------------------
__global__ void __launch_bounds__(256) k1_xw_hist(
        const float* __restrict__ x, const float* __restrict__ w_gcn,
        const int* __restrict__ ei32, int E) {
    const unsigned FULL = 0xFFFFFFFFu;
    // w_p[c2][k]: 64-bit pair (w[k][2c2], w[k][2c2+1]); pitch 256 ulls.
    __shared__ __align__(16) unsigned long long w_p[8 * F_IN];
    const int tid = threadIdx.x;
    const int lane = tid & 31;

    for (int i = tid; i < 8 * F_IN; i += 256) {
        int c2 = i & 7;
        int k = i >> 3;
        float2 p = ((const float2*)w_gcn)[k * 8 + c2];   // consecutive channels
        w_p[c2 * F_IN + k] = pack2f(p.x, p.y);
    }
    __syncthreads();

    const int gtid = blockIdx.x * blockDim.x + tid;
    const int nthreads = gridDim.x * blockDim.x;

    // Per-warp dtype probe: odd words 1..63 are 0 iff int64 layout.
    int oddw = ei32[2 * lane + 1];
    unsigned nz = __ballot_sync(FULL, oddw != 0);
    const bool is64 = (nz == 0);
    if (gtid == 0) g_idx_is64 = is64 ? 1 : 0;

    // 4-way sub histogram: spread per-address atomic queues 4x.
    int* hist = (int*)g_hist4;
    for (int e = gtid; e < E; e += nthreads) {
        int dst = is64 ? ei32[(size_t)2 * (E + e)] : ei32[(size_t)E + e];
        atomicAdd(&hist[dst * 4 + (e & 3)], 1);   // no return -> RED
    }

    const int warp = gtid >> 5;
    const int n0 = warp * 2;
    if (n0 >= N_NODES) return;

    const float4* __restrict__ xr4 = (const float4*)(x + (size_t)n0 * F_IN);
    const longlong2* wp2 = (const longlong2*)w_p;   // [c2][k/2], pitch 128

    unsigned long long a0[8], a1[8];
#pragma unroll
    for (int c2 = 0; c2 < 8; c2++) { a0[c2] = 0ull; a1[c2] = 0ull; }

#pragma unroll
    for (int i = 0; i < 2; i++) {
        int k4 = i * 32 + lane;                  // float4 index; k = 4*k4
        float4 xa = xr4[k4];                     // LDG.128, coalesced
        float4 xb = xr4[64 + k4];
        unsigned long long pa0 = pack2(xa.x), pa1 = pack2(xa.y),
                           pa2 = pack2(xa.z), pa3 = pack2(xa.w);
        unsigned long long pb0 = pack2(xb.x), pb1 = pack2(xb.y),
                           pb2 = pack2(xb.z), pb3 = pack2(xb.w);
#pragma unroll
        for (int c2 = 0; c2 < 8; c2++) {
            longlong2 wA = wp2[c2 * 128 + 2 * k4];       // LDS.128: k, k+1
            longlong2 wB = wp2[c2 * 128 + 2 * k4 + 1];   // LDS.128: k+2, k+3
            fma2(a0[c2], pa0, (unsigned long long)wA.x);
            fma2(a0[c2], pa1, (unsigned long long)wA.y);
            fma2(a0[c2], pa2, (unsigned long long)wB.x);
            fma2(a0[c2], pa3, (unsigned long long)wB.y);
            fma2(a1[c2], pb0, (unsigned long long)wA.x);
            fma2(a1[c2], pb1, (unsigned long long)wA.y);
            fma2(a1[c2], pb2, (unsigned long long)wB.x);
            fma2(a1[c2], pb3, (unsigned long long)wB.y);
        }
    }

    float f0[CH], f1[CH];
#pragma unroll
    for (int c2 = 0; c2 < 8; c2++) {
        unpack2(a0[c2], f0[2 * c2], f0[2 * c2 + 1]);
        unpack2(a1[c2], f1[2 * c2], f1[2 * c2 + 1]);
    }

    const int chan = chan_of_lane(lane);
    float s0 = reduce16(f0, lane);
    float s1 = reduce16(f1, lane);
    if (lane < 16) {
        g_h[(size_t)(n0 + 0) * CH + chan] = s0;
        g_h[(size_t)(n0 + 1) * CH + chan] = s1;
    }
}

// ---------------------------------------------------------------------------
// Launch 2: single-pass scan (decoupled lookback). Thread per dst: reads the
// int4 sub-counts, pads dst total to multiple of 8 (branch-free k2d), writes
// padded prefix + 4 sub-cursors. 98 blocks all resident -> spin is safe.
// Re-zeros g_hist4.
// ---------------------------------------------------------------------------
__global__ void k_scan() {
    __shared__ int s[SCAN_B];
    __shared__ int s_off;
    const int t = threadIdx.x;
    const int b = blockIdx.x;
    const int idx = b * SCAN_B + t;

    int4 hc = make_int4(0, 0, 0, 0);
    int v = 0;
    if (idx < N_NODES) {
        hc = g_hist4[idx];
        g_hist4[idx] = make_int4(0, 0, 0, 0);    // restore zero state
        int sum = hc.x + hc.y + hc.z + hc.w;
        v = (sum + 7) & ~7;                      // padded degree
    }
    s[t] = v;
    __syncthreads();
#pragma unroll
    for (int off = 1; off < SCAN_B; off <<= 1) {
        int u = (t >= off) ? s[t - off] : 0;
        __syncthreads();
        s[t] += u;
        __syncthreads();
    }

    if (t == 0) {
        s_off = 0;
        atomicExch(&g_bpub[b], s[SCAN_B - 1] | READY_BIT);   // publish own total
    }
    __syncthreads();

    if (t < b) {
        int u;
        do { u = atomicAdd(&g_bpub[t], 0); } while (!(u & READY_BIT));
        atomicAdd(&s_off, u & ~READY_BIT);
    }
    __syncthreads();

    int p = s[t] - v + s_off;            // global exclusive prefix (padded)
    if (idx < N_NODES) {
        g_ptr[idx] = p;
        g_cursor4[idx] = make_int4(p,
                                   p + hc.x,
                                   p + hc.x + hc.y,
                                   p + hc.x + hc.y + hc.z);
    }
    if (b == SCAN_NB - 1 && t == SCAN_B - 1)
        g_ptr[N_NODES] = s[t] + s_off;
}

// ---------------------------------------------------------------------------
// Launch 3: scatter edges into dst-grouped records via 4-way sub-cursors
// (per-address atomic queue depth 8 instead of 32). Resets lookback flags.
// ---------------------------------------------------------------------------
__global__ void k_scatter(const int* __restrict__ ei32,
                          const float* __restrict__ ew, int E) {
    if (blockIdx.x == 0 && threadIdx.x < SCAN_NB) g_bpub[threadIdx.x] = 0;

    int e = blockIdx.x * blockDim.x + threadIdx.x;
    if (e >= E) return;

    int src, dst;
    if (g_idx_is64) {
        src = ei32[(size_t)2 * e];
        dst = ei32[(size_t)2 * (E + e)];
    } else {
        src = ei32[e];
        dst = ei32[(size_t)E + e];
    }
    float w = ew[e];

    int* cur = (int*)g_cursor4;
    int p = atomicAdd(&cur[dst * 4 + (e & 3)], 1);
    g_rec[p] = make_int2(src << 6, __float_as_int(w));  // pre-scaled byte offset
}

// ---------------------------------------------------------------------------
// Launch 4: atomic-free aggregation FUSED with FCN head. One warp per node.
// Padded CSR -> branch-free loop; records hold src*64 so gather address is
// one IADD. Padding records (0,0) gather L1-hot row 0 with w=0.
// ---------------------------------------------------------------------------
__global__ void k2d_agg_head(const float* __restrict__ w0, const float* __restrict__ b0,
                             const float* __restrict__ w1, const float* __restrict__ b1,
                             float* __restrict__ out) {
    __shared__ float s_w0[CH * FCN];    // [c][f]: lane-consecutive reads
    __shared__ float s_w1[FCN];
    __shared__ float s_b0[FCN];
    __shared__ float s_b1;
    const int tid = threadIdx.x;
    for (int i = tid; i < CH * FCN; i += blockDim.x) s_w0[i] = w0[i];
    for (int i = tid; i < FCN; i += blockDim.x) { s_w1[i] = w1[i]; s_b0[i] = b0[i]; }
    if (tid == 0) s_b1 = b1[0];
    __syncthreads();

    const unsigned FULL = 0xFFFFFFFFu;
    int gtid = blockIdx.x * blockDim.x + tid;
    int n = gtid >> 5;
    if (n >= N_NODES) return;
    int lane = tid & 31;
    int slot = lane >> 2;               // 0..7
    const char* hbase = (const char*)g_h + ((lane & 3) << 4);

    int start = g_ptr[n];
    int end = g_ptr[n + 1];             // end-start is a multiple of 8

    float ax = 0.f, ay = 0.f, az = 0.f, aw = 0.f;

#pragma unroll 2
    for (int idx = start + slot; idx < end; idx += 8) {
        int2 r = g_rec[idx];                           // 4 lanes same addr: bcast
        float w = __int_as_float(r.y);
        const float4 hv = *(const float4*)(hbase + r.x);
        ax += hv.x * w; ay += hv.y * w; az += hv.z * w; aw += hv.w * w;
    }

    // Reduce across the 8 edge-slots: lanes 0-3 hold the 16 channels
#pragma unroll
    for (int m = 4; m <= 16; m <<= 1) {
        ax += __shfl_xor_sync(FULL, ax, m);
        ay += __shfl_xor_sync(FULL, ay, m);
        az += __shfl_xor_sync(FULL, az, m);
        aw += __shfl_xor_sync(FULL, aw, m);
    }

    // Broadcast the 16 channels (relu'd) to all lanes
    float a[CH];
#pragma unroll
    for (int q = 0; q < 4; q++) {
        a[4 * q + 0] = fmaxf(__shfl_sync(FULL, ax, q), 0.f);
        a[4 * q + 1] = fmaxf(__shfl_sync(FULL, ay, q), 0.f);
        a[4 * q + 2] = fmaxf(__shfl_sync(FULL, az, q), 0.f);
        a[4 * q + 3] = fmaxf(__shfl_sync(FULL, aw, q), 0.f);
    }

    // FCN head: lane l computes units f=l and f=l+32.
    float o1a = s_b0[lane];
    float o1b = s_b0[lane + 32];
#pragma unroll
    for (int c = 0; c < CH; c++) {
        o1a += a[c] * s_w0[c * FCN + lane];        // conflict-free LDS
        o1b += a[c] * s_w0[c * FCN + lane + 32];
    }
    o1a = fmaxf(o1a, 0.f);
    o1b = fmaxf(o1b, 0.f);
    float o2 = o1a * s_w1[lane] + o1b * s_w1[lane + 32];
#pragma unroll
    for (int m = 16; m > 0; m >>= 1)
        o2 += __shfl_xor_sync(FULL, o2, m);
    if (lane == 0) out[n] = o2 + s_b1;
}

// ---------------------------------------------------------------------------
// Launcher. Inputs identified by element count (robust to ordering):
//   x: 25,600,000   edge_index: 6,400,000   edge_w: 3,200,000
//   w_gcn: 4096     w0: 1024   b0: 64 (first)   w1: 64 (second)   b1: 1
// ---------------------------------------------------------------------------
extern "C" void kernel_launch(void* const* d_in, const int* in_sizes, int n_in,
                              void* d_out, int out_size) {
    const float* x = nullptr;
    const int* ei = nullptr;
    const float* ew = nullptr;
    const float* wg = nullptr;
    const float* w0 = nullptr;
    const float* b0 = nullptr;
    const float* w1 = nullptr;
    const float* b1 = nullptr;
    int E = 0;
    int seen64 = 0;

    for (int i = 0; i < n_in; i++) {
        int s = in_sizes[i];
        if (s == N_NODES * F_IN)      x  = (const float*)d_in[i];
        else if (s == 2 * N_EDGES)    { ei = (const int*)d_in[i]; E = s / 2; }
        else if (s == N_EDGES)        ew = (const float*)d_in[i];
        else if (s == F_IN * CH)      wg = (const float*)d_in[i];
        else if (s == CH * FCN)       w0 = (const float*)d_in[i];
        else if (s == FCN)            { if (seen64++ == 0) b0 = (const float*)d_in[i];
                                        else               w1 = (const float*)d_in[i]; }
        else if (s == 1)              b1 = (const float*)d_in[i];
    }

    float* out = (float*)d_out;

    // Launch 1: GEMV (2 nodes/warp, f32x2) + 4-way sub histogram + probe
    {
        int warps = N_NODES / 2;                 // 50000
        int blocks = warps * 32 / 256;           // 6250
        k1_xw_hist<<<blocks, 256>>>(x, wg, ei, E);
    }

    // Launch 2: single-pass lookback scan (padded degrees, sub-cursors)
    k_scan<<<SCAN_NB, SCAN_B>>>();

    // Launch 3: scatter via sub-cursors
    k_scatter<<<(N_EDGES + 255) / 256, 256>>>(ei, ew, E);

    // Launch 4: atomic-free aggregation + FCN head, warp per node
    k2d_agg_head<<<(N_NODES * 32 + 255) / 256, 256>>>(w0, b0, w1, b1, out);
}

// round 12
// speedup vs baseline: 1.1200x; 1.1200x over previous
#include <cuda_runtime.h>
#include <cuda_bf16.h>
#include <cstdint>

#define N_NODES 100000
#define N_EDGES 3200000
#define F_IN 256
#define CH 16
#define FCN 64

#define SCAN_B 1024
#define SCAN_NB ((N_NODES + SCAN_B - 1) / SCAN_B)   // 98
#define READY_BIT 0x40000000

#define REC_CAP (N_EDGES + 8 * N_NODES)              // padded CSR capacity

// Scratch: __device__ globals (no allocation allowed). Statically zeroed at
// load; kernels restore zero state each call (scan re-zeros hist; scatter
// resets bpub). CSR padding slots are never written -> stay (0,0) forever:
// src_off=0, w=0 contributes nothing (gathers L1-hot row 0).
__device__ __align__(128) float g_h[N_NODES * CH];
__device__ __align__(128) int2  g_rec[REC_CAP];       // (src*64, w_bits), dst-grouped
__device__ int g_hist[N_NODES];                       // zero-init; re-zeroed in k_scan
__device__ int g_ptr[N_NODES + 1];                    // padded-degree prefix
__device__ int g_cursor[N_NODES];
__device__ int g_bpub[SCAN_NB];                       // zero-init; reset in scatter
__device__ int g_idx_is64;                            // published by k1

// ---------------------------------------------------------------------------
// log-halving cross-lane reduction of 16 per-channel partials over 32 lanes.
// 16 shfls instead of 80. Channel chan_of_lane(lane) ends on lane (and l^16).
// ---------------------------------------------------------------------------
__device__ __forceinline__ float reduce16(const float* r, int lane) {
    const unsigned FULL = 0xFFFFFFFFu;
    float t[8];
    bool hi = (lane & 1);
#pragma unroll
    for (int j = 0; j < 8; j++) {
        float give = hi ? r[j] : r[j + 8];
        float keep = hi ? r[j + 8] : r[j];
        t[j] = keep + __shfl_xor_sync(FULL, give, 1);
    }
    float u[4];
    hi = (lane & 2);
#pragma unroll
    for (int j = 0; j < 4; j++) {
        float give = hi ? t[j] : t[j + 4];
        float keep = hi ? t[j + 4] : t[j];
        u[j] = keep + __shfl_xor_sync(FULL, give, 2);
    }
    hi = (lane & 4);
    float g0 = hi ? u[0] : u[2];
    float k0 = hi ? u[2] : u[0];
    float v0 = k0 + __shfl_xor_sync(FULL, g0, 4);
    float g1 = hi ? u[1] : u[3];
    float k1 = hi ? u[3] : u[1];
    float v1 = k1 + __shfl_xor_sync(FULL, g1, 4);

    hi = (lane & 8);
    float g2 = hi ? v0 : v1;
    float k2 = hi ? v1 : v0;
    float w = k2 + __shfl_xor_sync(FULL, g2, 8);

    w += __shfl_xor_sync(FULL, w, 16);
    return w;
}

__device__ __forceinline__ int chan_of_lane(int lane) {
    return ((lane & 1) << 3) | ((lane & 2) << 1) | ((lane & 4) >> 1) | ((lane & 8) >> 3);
}

// ---------------------------------------------------------------------------
// Launch 1: h = x @ w_gcn (4 nodes/warp, float4 loads, LDS.128 weights)
// + dtype probe + fused dst histogram, 4 edges/thread via int4 loads
// (800K threads exactly cover E/4). REDs hide under the DRAM-bound x read.
// ---------------------------------------------------------------------------
__global__ void __launch_bounds__(256) k1_xw_hist(
        const float* __restrict__ x, const float* __restrict__ w_gcn,
        const int* __restrict__ ei32, int E) {
    const unsigned FULL = 0xFFFFFFFFu;
    __shared__ __align__(16) float w_t[F_IN * CH];   // [c][k], pitch 256
    const int tid = threadIdx.x;
    for (int i = tid; i < F_IN * CH; i += 256) {
        int k = i >> 4;
        int c = i & 15;
        w_t[c * F_IN + k] = w_gcn[i];
    }
    __syncthreads();

    const int gtid = blockIdx.x * blockDim.x + tid;
    const int lane = tid & 31;

    // Per-warp dtype probe: odd words 1..63 are 0 iff int64 layout.
    int oddw = ei32[2 * lane + 1];
    unsigned nz = __ballot_sync(FULL, oddw != 0);
    const bool is64 = (nz == 0);
    if (gtid == 0) g_idx_is64 = is64 ? 1 : 0;

    // Histogram: 4 edges per thread, independent REDs in flight.
    {
        int e = gtid * 4;
        if (e + 3 < E) {
            int d0, d1, d2, d3;
            if (is64) {
                int4 pa = *(const int4*)(ei32 + (size_t)2 * (E + e));
                int4 pb = *(const int4*)(ei32 + (size_t)2 * (E + e) + 4);
                d0 = pa.x; d1 = pa.z; d2 = pb.x; d3 = pb.z;
            } else {
                int4 p = *(const int4*)(ei32 + (size_t)E + e);
                d0 = p.x; d1 = p.y; d2 = p.z; d3 = p.w;
            }
            atomicAdd(&g_hist[d0], 1);
            atomicAdd(&g_hist[d1], 1);
            atomicAdd(&g_hist[d2], 1);
            atomicAdd(&g_hist[d3], 1);
        } else {
            for (int q = 0; q < 4 && e + q < E; q++) {
                int dst = is64 ? ei32[(size_t)2 * (E + e + q)]
                               : ei32[(size_t)E + e + q];
                atomicAdd(&g_hist[dst], 1);
            }
        }
    }

    const int warp = gtid >> 5;
    const int n0 = warp * 4;
    if (n0 >= N_NODES) return;       // N_NODES % 4 == 0

    const float4* __restrict__ xr4 = (const float4*)(x + (size_t)n0 * F_IN);
    const float4* wt4 = (const float4*)w_t;          // [c][k4], pitch 64

    float acc0[CH], acc1[CH], acc2[CH], acc3[CH];
#pragma unroll
    for (int c = 0; c < CH; c++) { acc0[c] = acc1[c] = acc2[c] = acc3[c] = 0.f; }

#pragma unroll
    for (int i = 0; i < 2; i++) {
        int k4 = i * 32 + lane;                      // float4 column index
        float4 xa = xr4[k4];                         // LDG.128, coalesced
        float4 xb = xr4[64 + k4];
        float4 xc = xr4[128 + k4];
        float4 xd = xr4[192 + k4];
#pragma unroll
        for (int c = 0; c < CH; c++) {
            float4 wv = wt4[c * 64 + k4];            // LDS.128, conflict-free
            acc0[c] += xa.x * wv.x + xa.y * wv.y + xa.z * wv.z + xa.w * wv.w;
            acc1[c] += xb.x * wv.x + xb.y * wv.y + xb.z * wv.z + xb.w * wv.w;
            acc2[c] += xc.x * wv.x + xc.y * wv.y + xc.z * wv.z + xc.w * wv.w;
            acc3[c] += xd.x * wv.x + xd.y * wv.y + xd.z * wv.z + xd.w * wv.w;
        }
    }

    const int chan = chan_of_lane(lane);
    float s0 = reduce16(acc0, lane);
    float s1 = reduce16(acc1, lane);
    float s2 = reduce16(acc2, lane);
    float s3 = reduce16(acc3, lane);
    if (lane < 16) {
        g_h[(size_t)(n0 + 0) * CH + chan] = s0;
        g_h[(size_t)(n0 + 1) * CH + chan] = s1;
        g_h[(size_t)(n0 + 2) * CH + chan] = s2;
        g_h[(size_t)(n0 + 3) * CH + chan] = s3;
    }
}

// ---------------------------------------------------------------------------
// Launch 2: single-pass scan (decoupled lookback) over PADDED degrees
// (multiple of 8 -> branch-free k2d). 98 blocks all resident -> spin is
// deadlock-free. Re-zeros g_hist.
// ---------------------------------------------------------------------------
__global__ void k_scan() {
    __shared__ int s[SCAN_B];
    __shared__ int s_off;
    const int t = threadIdx.x;
    const int b = blockIdx.x;
    const int idx = b * SCAN_B + t;

    int v = 0;
    if (idx < N_NODES) {
        int d = g_hist[idx];
        g_hist[idx] = 0;                 // restore zero state for next call
        v = (d + 7) & ~7;                // padded degree
    }
    s[t] = v;
    __syncthreads();
#pragma unroll
    for (int off = 1; off < SCAN_B; off <<= 1) {
        int u = (t >= off) ? s[t - off] : 0;
        __syncthreads();
        s[t] += u;
        __syncthreads();
    }

    if (t == 0) {
        s_off = 0;
        atomicExch(&g_bpub[b], s[SCAN_B - 1] | READY_BIT);   // publish own total
    }
    __syncthreads();

    if (t < b) {
        int u;
        do { u = atomicAdd(&g_bpub[t], 0); } while (!(u & READY_BIT));
        atomicAdd(&s_off, u & ~READY_BIT);
    }
    __syncthreads();

    int p = s[t] - v + s_off;            // global exclusive prefix (padded)
    if (idx < N_NODES) {
        g_ptr[idx] = p;
        g_cursor[idx] = p;
    }
    if (b == SCAN_NB - 1 && t == SCAN_B - 1)
        g_ptr[N_NODES] = s[t] + s_off;
}

// ---------------------------------------------------------------------------
// Launch 3: scatter, 4 edges per thread. int4/float4 coalesced loads, then
// 4 INDEPENDENT atomic+store chains in flight (MLP 4 in the ~318cyc ATOMG
// window) -- the kernel was latency-bound at issue=6%. Resets lookback flags.
// ---------------------------------------------------------------------------
__global__ void __launch_bounds__(256) k_scatter(
        const int* __restrict__ ei32, const float* __restrict__ ew, int E) {
    if (blockIdx.x == 0 && threadIdx.x < SCAN_NB) g_bpub[threadIdx.x] = 0;

    int gtid = blockIdx.x * blockDim.x + threadIdx.x;
    int e = gtid * 4;
    if (e >= E) return;

    int s0, s1, s2, s3, d0, d1, d2, d3;
    if (g_idx_is64) {
        int4 sa = *(const int4*)(ei32 + (size_t)2 * e);
        int4 sb = *(const int4*)(ei32 + (size_t)2 * e + 4);
        int4 da = *(const int4*)(ei32 + (size_t)2 * (E + e));
        int4 db = *(const int4*)(ei32 + (size_t)2 * (E + e) + 4);
        s0 = sa.x; s1 = sa.z; s2 = sb.x; s3 = sb.z;
        d0 = da.x; d1 = da.z; d2 = db.x; d3 = db.z;
    } else {
        int4 sv = *(const int4*)(ei32 + e);
        int4 dv = *(const int4*)(ei32 + (size_t)E + e);
        s0 = sv.x; s1 = sv.y; s2 = sv.z; s3 = sv.w;
        d0 = dv.x; d1 = dv.y; d2 = dv.z; d3 = dv.w;
    }
    float4 wv = *(const float4*)(ew + e);

    // 4 independent atomic->store chains (hardware keeps all in flight).
    int p0 = atomicAdd(&g_cursor[d0], 1);
    int p1 = atomicAdd(&g_cursor[d1], 1);
    int p2 = atomicAdd(&g_cursor[d2], 1);
    int p3 = atomicAdd(&g_cursor[d3], 1);
    g_rec[p0] = make_int2(s0 << 6, __float_as_int(wv.x));
    g_rec[p1] = make_int2(s1 << 6, __float_as_int(wv.y));
    g_rec[p2] = make_int2(s2 << 6, __float_as_int(wv.z));
    g_rec[p3] = make_int2(s3 << 6, __float_as_int(wv.w));
}

// ---------------------------------------------------------------------------
// Launch 4: atomic-free aggregation FUSED with FCN head. One warp per node.
// Padded CSR -> branch-free loop; records hold src*64 so gather address is
// one IADD. Padding records (0,0) gather L1-hot row 0 with w=0.
// ---------------------------------------------------------------------------
__global__ void k2d_agg_head(const float* __restrict__ w0, const float* __restrict__ b0,
                             const float* __restrict__ w1, const float* __restrict__ b1,
                             float* __restrict__ out) {
    __shared__ float s_w0[CH * FCN];    // [c][f]: lane-consecutive reads
    __shared__ float s_w1[FCN];
    __shared__ float s_b0[FCN];
    __shared__ float s_b1;
    const int tid = threadIdx.x;
    for (int i = tid; i < CH * FCN; i += blockDim.x) s_w0[i] = w0[i];
    for (int i = tid; i < FCN; i += blockDim.x) { s_w1[i] = w1[i]; s_b0[i] = b0[i]; }
    if (tid == 0) s_b1 = b1[0];
    __syncthreads();

    const unsigned FULL = 0xFFFFFFFFu;
    int gtid = blockIdx.x * blockDim.x + tid;
    int n = gtid >> 5;
    if (n >= N_NODES) return;
    int lane = tid & 31;
    int slot = lane >> 2;               // 0..7
    const char* hbase = (const char*)g_h + ((lane & 3) << 4);

    int start = g_ptr[n];
    int end = g_ptr[n + 1];             // end-start is a multiple of 8

    float ax = 0.f, ay = 0.f, az = 0.f, aw = 0.f;

#pragma unroll 2
    for (int idx = start + slot; idx < end; idx += 8) {
        int2 r = g_rec[idx];                           // 4 lanes same addr: bcast
        float w = __int_as_float(r.y);
        const float4 hv = *(const float4*)(hbase + r.x);
        ax += hv.x * w; ay += hv.y * w; az += hv.z * w; aw += hv.w * w;
    }

    // Reduce across the 8 edge-slots: lanes 0-3 hold the 16 channels
#pragma unroll
    for (int m = 4; m <= 16; m <<= 1) {
        ax += __shfl_xor_sync(FULL, ax, m);
        ay += __shfl_xor_sync(FULL, ay, m);
        az += __shfl_xor_sync(FULL, az, m);
        aw += __shfl_xor_sync(FULL, aw, m);
    }

    // Broadcast the 16 channels (relu'd) to all lanes
    float a[CH];
#pragma unroll
    for (int q = 0; q < 4; q++) {
        a[4 * q + 0] = fmaxf(__shfl_sync(FULL, ax, q), 0.f);
        a[4 * q + 1] = fmaxf(__shfl_sync(FULL, ay, q), 0.f);
        a[4 * q + 2] = fmaxf(__shfl_sync(FULL, az, q), 0.f);
        a[4 * q + 3] = fmaxf(__shfl_sync(FULL, aw, q), 0.f);
    }

    // FCN head: lane l computes units f=l and f=l+32.
    float o1a = s_b0[lane];
    float o1b = s_b0[lane + 32];
#pragma unroll
    for (int c = 0; c < CH; c++) {
        o1a += a[c] * s_w0[c * FCN + lane];        // conflict-free LDS
        o1b += a[c] * s_w0[c * FCN + lane + 32];
    }
    o1a = fmaxf(o1a, 0.f);
    o1b = fmaxf(o1b, 0.f);
    float o2 = o1a * s_w1[lane] + o1b * s_w1[lane + 32];
#pragma unroll
    for (int m = 16; m > 0; m >>= 1)
        o2 += __shfl_xor_sync(FULL, o2, m);
    if (lane == 0) out[n] = o2 + s_b1;
}

// ---------------------------------------------------------------------------
// Launcher. Inputs identified by element count (robust to ordering):
//   x: 25,600,000   edge_index: 6,400,000   edge_w: 3,200,000
//   w_gcn: 4096     w0: 1024   b0: 64 (first)   w1: 64 (second)   b1: 1
// ---------------------------------------------------------------------------
extern "C" void kernel_launch(void* const* d_in, const int* in_sizes, int n_in,
                              void* d_out, int out_size) {
    const float* x = nullptr;
    const int* ei = nullptr;
    const float* ew = nullptr;
    const float* wg = nullptr;
    const float* w0 = nullptr;
    const float* b0 = nullptr;
    const float* w1 = nullptr;
    const float* b1 = nullptr;
    int E = 0;
    int seen64 = 0;

    for (int i = 0; i < n_in; i++) {
        int s = in_sizes[i];
        if (s == N_NODES * F_IN)      x  = (const float*)d_in[i];
        else if (s == 2 * N_EDGES)    { ei = (const int*)d_in[i]; E = s / 2; }
        else if (s == N_EDGES)        ew = (const float*)d_in[i];
        else if (s == F_IN * CH)      wg = (const float*)d_in[i];
        else if (s == CH * FCN)       w0 = (const float*)d_in[i];
        else if (s == FCN)            { if (seen64++ == 0) b0 = (const float*)d_in[i];
                                        else               w1 = (const float*)d_in[i]; }
        else if (s == 1)              b1 = (const float*)d_in[i];
    }

    float* out = (float*)d_out;

    // Launch 1: GEMV (4 nodes/warp) + probe + histogram (4 edges/thread)
    {
        int warps = N_NODES / 4;                 // 25000 -> 800K threads = E/4
        int blocks = warps * 32 / 256;           // 3125
        k1_xw_hist<<<blocks, 256>>>(x, wg, ei, E);
    }

    // Launch 2: single-pass lookback scan (padded degrees)
    k_scan<<<SCAN_NB, SCAN_B>>>();

    // Launch 3: scatter, 4 edges/thread (MLP 4)
    k_scatter<<<(N_EDGES / 4 + 255) / 256, 256>>>(ei, ew, E);

    // Launch 4: atomic-free aggregation + FCN head, warp per node
    k2d_agg_head<<<(N_NODES * 32 + 255) / 256, 256>>>(w0, b0, w1, b1, out);
}